// round 1
// baseline (speedup 1.0000x reference)
#include <cuda_runtime.h>

using ull = unsigned long long;

// ---------- packed f32x2 + MUFU helpers ----------
__device__ __forceinline__ ull pk2(float lo, float hi) {
    ull r; asm("mov.b64 %0, {%1, %2};" : "=l"(r) : "f"(lo), "f"(hi)); return r;
}
__device__ __forceinline__ void upk2(ull v, float& lo, float& hi) {
    asm("mov.b64 {%0, %1}, %2;" : "=f"(lo), "=f"(hi) : "l"(v));
}
__device__ __forceinline__ ull fma2(ull a, ull b, ull c) {
    ull d; asm("fma.rn.f32x2 %0, %1, %2, %3;" : "=l"(d) : "l"(a), "l"(b), "l"(c)); return d;
}
__device__ __forceinline__ ull add2(ull a, ull b) {
    ull d; asm("add.rn.f32x2 %0, %1, %2;" : "=l"(d) : "l"(a), "l"(b)); return d;
}
__device__ __forceinline__ float ex2f(float x) {
    float y; asm("ex2.approx.f32 %0, %1;" : "=f"(y) : "f"(x)); return y;
}
__device__ __forceinline__ float rcpf(float x) {
    float y; asm("rcp.approx.f32 %0, %1;" : "=f"(y) : "f"(x)); return y;
}
// sigmoid(x) = 1 / (1 + 2^(-x*log2e))
__device__ __forceinline__ float sigm(float x) {
    return rcpf(1.0f + ex2f(x * -1.4426950408889634f));
}
// tanh(x) = 1 - 2/(2^(2x*log2e) + 1)   (stable both directions)
__device__ __forceinline__ float tanhx(float x) {
    return fmaf(-2.0f, rcpf(1.0f + ex2f(x * 2.8853900817779268f)), 1.0f);
}

// Hidden split across a quad of threads: roles {0,1} own 3 hidden units,
// roles {2,3} own 2. PyTorch gate order i,f,g,o -> rows j, 10+j, 20+j, 30+j.
#define HID 10

__global__ void __launch_bounds__(128, 1)
lstm_seq_kernel(const float* __restrict__ x,
                const float* __restrict__ w_ih,
                const float* __restrict__ w_hh,
                const float* __restrict__ b_ih,
                const float* __restrict__ b_hh,
                const float* __restrict__ fc_w,
                const float* __restrict__ fc_b,
                float* __restrict__ out,
                int S, int B)
{
    const int gtid = blockIdx.x * blockDim.x + threadIdx.x;
    const int role = gtid & 3;
    const int b    = gtid >> 2;
    if (b >= B) return;

    const int jbase = (role < 2) ? role * 3 : 2 + role * 2;  // 0,3,6,8
    const int nj    = (role < 2) ? 3 : 2;

    // ---- per-thread weights in registers ----
    // whhA[jj][k] = (w_hh[i-gate row][k], w_hh[f-gate row][k])  packed
    // whhB[jj][k] = (g, o) pair
    ull whhA[3][HID], whhB[3][HID];
    ull wx2A[3], wx2B[3], b2A[3], b2B[3];

#pragma unroll
    for (int jj = 0; jj < 3; ++jj) {
        float wxi = 0.f, wxf = 0.f, wxg = 0.f, wxo = 0.f;
        float bi = 0.f, bf = 0.f, bg = 0.f, bo = 0.f;
        if (jj < nj) {
            int j = jbase + jj;
            wxi = w_ih[j];            wxf = w_ih[HID + j];
            wxg = w_ih[2 * HID + j];  wxo = w_ih[3 * HID + j];
            bi  = b_ih[j]           + b_hh[j];
            bf  = b_ih[HID + j]     + b_hh[HID + j];
            bg  = b_ih[2 * HID + j] + b_hh[2 * HID + j];
            bo  = b_ih[3 * HID + j] + b_hh[3 * HID + j];
#pragma unroll
            for (int k = 0; k < HID; ++k) {
                whhA[jj][k] = pk2(w_hh[j * HID + k],
                                  w_hh[(HID + j) * HID + k]);
                whhB[jj][k] = pk2(w_hh[(2 * HID + j) * HID + k],
                                  w_hh[(3 * HID + j) * HID + k]);
            }
        } else {
#pragma unroll
            for (int k = 0; k < HID; ++k) { whhA[jj][k] = 0ull; whhB[jj][k] = 0ull; }
        }
        wx2A[jj] = pk2(wxi, wxf);  wx2B[jj] = pk2(wxg, wxo);
        b2A[jj]  = pk2(bi, bf);    b2B[jj]  = pk2(bg, bo);
    }

    float fc[HID];
#pragma unroll
    for (int j = 0; j < HID; ++j) fc[j] = fc_w[j];
    const float fb = fc_b[0];

    // ---- state ----
    ull   hd[HID];                       // h[k] duplicated into both f32x2 lanes
#pragma unroll
    for (int k = 0; k < HID; ++k) hd[k] = 0ull;
    float cst[3]  = {0.f, 0.f, 0.f};

    const float* xp = x + b;
    float* op = out + b;
    float xv = __ldg(xp);                // prefetch t=0

    for (int t = 0; t < S; ++t) {
        const float xt = xv;
        const int tn = (t + 1 < S) ? t + 1 : t;
        xv = __ldg(xp + (size_t)tn * B); // prefetch next step (hidden under compute)

        const ull xd = pk2(xt, xt);
        float hnew[3] = {0.f, 0.f, 0.f};

#pragma unroll
        for (int jj = 0; jj < 3; ++jj) {
            if (jj < nj) {
                // split even/odd-k accumulators to halve the serial FMA chain
                ull a0 = fma2(xd, wx2A[jj], b2A[jj]);
                ull a1 = fma2(hd[1], whhA[jj][1], 0ull);
                ull q0 = fma2(xd, wx2B[jj], b2B[jj]);
                ull q1 = fma2(hd[1], whhB[jj][1], 0ull);
#pragma unroll
                for (int k = 0; k < HID; k += 2) {
                    a0 = fma2(hd[k], whhA[jj][k], a0);
                    q0 = fma2(hd[k], whhB[jj][k], q0);
                }
#pragma unroll
                for (int k = 3; k < HID; k += 2) {
                    a1 = fma2(hd[k], whhA[jj][k], a1);
                    q1 = fma2(hd[k], whhB[jj][k], q1);
                }
                const ull accA = add2(a0, a1);
                const ull accB = add2(q0, q1);

                float gi, gf, gg, go;
                upk2(accA, gi, gf);
                upk2(accB, gg, go);

                const float ia = sigm(gi);
                const float fa = sigm(gf);
                const float ga = tanhx(gg);
                const float oa = sigm(go);

                const float cn = fmaf(ia, ga, fa * cst[jj]);
                cst[jj] = cn;
                hnew[jj] = oa * tanhx(cn);
            }
        }

        // ---- broadcast new h across the quad (width-4 shuffles) ----
        float hs[HID];
        hs[0] = __shfl_sync(0xffffffffu, hnew[0], 0, 4);
        hs[1] = __shfl_sync(0xffffffffu, hnew[1], 0, 4);
        hs[2] = __shfl_sync(0xffffffffu, hnew[2], 0, 4);
        hs[3] = __shfl_sync(0xffffffffu, hnew[0], 1, 4);
        hs[4] = __shfl_sync(0xffffffffu, hnew[1], 1, 4);
        hs[5] = __shfl_sync(0xffffffffu, hnew[2], 1, 4);
        hs[6] = __shfl_sync(0xffffffffu, hnew[0], 2, 4);
        hs[7] = __shfl_sync(0xffffffffu, hnew[1], 2, 4);
        hs[8] = __shfl_sync(0xffffffffu, hnew[0], 3, 4);
        hs[9] = __shfl_sync(0xffffffffu, hnew[1], 3, 4);

        // output head + re-duplicate h for next step's packed dots
        float yv = fb;
#pragma unroll
        for (int j = 0; j < HID; ++j) {
            yv = fmaf(hs[j], fc[j], yv);
            hd[j] = pk2(hs[j], hs[j]);
        }

        if (role == 0) op[(size_t)t * B] = yv;
    }
}

extern "C" void kernel_launch(void* const* d_in, const int* in_sizes, int n_in,
                              void* d_out, int out_size)
{
    const float* x    = (const float*)d_in[0];
    const float* w_ih = (const float*)d_in[1];
    const float* w_hh = (const float*)d_in[2];
    const float* b_ih = (const float*)d_in[3];
    const float* b_hh = (const float*)d_in[4];
    const float* fc_w = (const float*)d_in[5];
    const float* fc_b = (const float*)d_in[6];
    float* out = (float*)d_out;

    const int B = 4096;
    const int S = in_sizes[0] / B;   // 2048

    const int threads = 128;                  // 32 batch elems / block
    const int blocks  = (B * 4) / threads;    // 128 blocks -> 1 per SM, 1 warp/SMSP

    lstm_seq_kernel<<<blocks, threads>>>(x, w_ih, w_hh, b_ih, b_hh,
                                         fc_w, fc_b, out, S, B);
}

// round 2
// speedup vs baseline: 1.3262x; 1.3262x over previous
#include <cuda_runtime.h>

using ull = unsigned long long;

// ---------- packed f32x2 + MUFU helpers ----------
__device__ __forceinline__ ull pk2(float lo, float hi) {
    ull r; asm("mov.b64 %0, {%1, %2};" : "=l"(r) : "f"(lo), "f"(hi)); return r;
}
__device__ __forceinline__ void upk2(ull v, float& lo, float& hi) {
    asm("mov.b64 {%0, %1}, %2;" : "=f"(lo), "=f"(hi) : "l"(v));
}
__device__ __forceinline__ ull fma2(ull a, ull b, ull c) {
    ull d; asm("fma.rn.f32x2 %0, %1, %2, %3;" : "=l"(d) : "l"(a), "l"(b), "l"(c)); return d;
}
__device__ __forceinline__ ull add2(ull a, ull b) {
    ull d; asm("add.rn.f32x2 %0, %1, %2;" : "=l"(d) : "l"(a), "l"(b)); return d;
}
__device__ __forceinline__ ull mul2(ull a, ull b) {
    ull d; asm("mul.rn.f32x2 %0, %1, %2;" : "=l"(d) : "l"(a), "l"(b)); return d;
}
__device__ __forceinline__ float ex2f(float x) {
    float y; asm("ex2.approx.f32 %0, %1;" : "=f"(y) : "f"(x)); return y;
}
__device__ __forceinline__ float rcpf(float x) {
    float y; asm("rcp.approx.f32 %0, %1;" : "=f"(y) : "f"(x)); return y;
}

#define HID 10
#define L2E 1.4426950408889634f

// Layout: 10 lanes per batch element (1 hidden unit per lane), 3 elems per
// warp (lanes 30,31 idle-duplicate). Each lane computes all 4 gates for its
// hidden unit j with register-resident packed weights, then the 10 new h
// values are re-broadcast within the group via shfl.idx.
__global__ void __launch_bounds__(128, 4)
lstm_lane10_kernel(const float* __restrict__ x,
                   const float* __restrict__ w_ih,
                   const float* __restrict__ w_hh,
                   const float* __restrict__ b_ih,
                   const float* __restrict__ b_hh,
                   const float* __restrict__ fc_w,
                   const float* __restrict__ fc_b,
                   float* __restrict__ out,
                   int S, int B)
{
    const int lane = threadIdx.x & 31;
    const int wg   = blockIdx.x * (blockDim.x >> 5) + (threadIdx.x >> 5);

    int grp = lane / HID; if (grp > 2) grp = 2;          // lanes 30,31 -> group 2
    int j   = lane - grp * HID; if (j >= HID) j = HID - 1; // clamp for lanes 30,31
    const int gbase = grp * HID;

    int b = wg * 3 + grp;
    const bool live = (b < B);
    if (b >= B) b = B - 1;                                // clamp for safe loads

    // ---- per-lane weights in registers ----
    // whhA[k] = (w_hh[i-row j][k], w_hh[f-row][k]); whhB[k] = (g-row, o-row)
    ull whhA[HID], whhB[HID];
#pragma unroll
    for (int k = 0; k < HID; ++k) {
        whhA[k] = pk2(w_hh[j * HID + k],           w_hh[(HID + j) * HID + k]);
        whhB[k] = pk2(w_hh[(2 * HID + j) * HID + k], w_hh[(3 * HID + j) * HID + k]);
    }
    const ull wx2A = pk2(w_ih[j],           w_ih[HID + j]);
    const ull wx2B = pk2(w_ih[2 * HID + j], w_ih[3 * HID + j]);
    const ull b2A  = pk2(b_ih[j] + b_hh[j],
                         b_ih[HID + j] + b_hh[HID + j]);
    const ull b2B  = pk2(b_ih[2 * HID + j] + b_hh[2 * HID + j],
                         b_ih[3 * HID + j] + b_hh[3 * HID + j]);

    float fc[HID];
#pragma unroll
    for (int k = 0; k < HID; ++k) fc[k] = fc_w[k];
    const float fb = fc_b[0];

    // packed activation pre-scale constants
    const ull cIF = pk2(-L2E, -L2E);          // (i, f) sigmoids
    const ull cGO = pk2(2.0f * L2E, -L2E);    // (g tanh, o sigmoid)

    // ---- state ----
    ull hd[HID];
#pragma unroll
    for (int k = 0; k < HID; ++k) hd[k] = 0ull;
    float c = 0.f;

    const float* xp = x + b;
    float* op = out + b;
    float xv = __ldg(xp);                    // prefetch t=0

    for (int t = 0; t < S; ++t) {
        const float xt = xv;
        const int tn = (t + 1 < S) ? t + 1 : t;
        xv = __ldg(xp + (size_t)tn * B);     // prefetch next step

        const ull xd = pk2(xt, xt);

        // gate dot products, even/odd-k split accumulators
        ull a0 = fma2(xd, wx2A, b2A);
        ull q0 = fma2(xd, wx2B, b2B);
        ull a1 = fma2(hd[1], whhA[1], 0ull);
        ull q1 = fma2(hd[1], whhB[1], 0ull);
#pragma unroll
        for (int k = 0; k < HID; k += 2) {
            a0 = fma2(hd[k], whhA[k], a0);
            q0 = fma2(hd[k], whhB[k], q0);
        }
#pragma unroll
        for (int k = 3; k < HID; k += 2) {
            a1 = fma2(hd[k], whhA[k], a1);
            q1 = fma2(hd[k], whhB[k], q1);
        }
        const ull accA = add2(a0, a1);   // (gate_i, gate_f)
        const ull accB = add2(q0, q1);   // (gate_g, gate_o)

        // activations
        float si, sf, sg, so;
        upk2(mul2(accA, cIF), si, sf);
        upk2(mul2(accB, cGO), sg, so);
        const float ia = rcpf(1.0f + ex2f(si));
        const float fa = rcpf(1.0f + ex2f(sf));
        const float ga = fmaf(-2.0f, rcpf(1.0f + ex2f(sg)), 1.0f);
        const float oa = rcpf(1.0f + ex2f(so));

        const float cn = fmaf(ia, ga, fa * c);
        c = cn;
        const float tc = fmaf(-2.0f, rcpf(1.0f + ex2f(cn * (2.0f * L2E))), 1.0f);
        const float hn = oa * tc;

        // re-broadcast the group's 10 h values (shfl.idx, width 32)
        float hs[HID];
#pragma unroll
        for (int m = 0; m < HID; ++m)
            hs[m] = __shfl_sync(0xffffffffu, hn, gbase + m, 32);

        // output head + repack h for next step's packed dots
        float yv = fb;
#pragma unroll
        for (int m = 0; m < HID; ++m) {
            yv = fmaf(hs[m], fc[m], yv);
            hd[m] = pk2(hs[m], hs[m]);
        }

        if (live && j == 0) op[(size_t)t * B] = yv;
    }
}

extern "C" void kernel_launch(void* const* d_in, const int* in_sizes, int n_in,
                              void* d_out, int out_size)
{
    const float* x    = (const float*)d_in[0];
    const float* w_ih = (const float*)d_in[1];
    const float* w_hh = (const float*)d_in[2];
    const float* b_ih = (const float*)d_in[3];
    const float* b_hh = (const float*)d_in[4];
    const float* fc_w = (const float*)d_in[5];
    const float* fc_b = (const float*)d_in[6];
    float* out = (float*)d_out;

    const int B = 4096;
    const int S = in_sizes[0] / B;   // 2048

    const int threads = 128;                       // 4 warps = 12 elems/block
    const int elems_per_block = 12;
    const int blocks = (B + elems_per_block - 1) / elems_per_block;  // 342

    lstm_lane10_kernel<<<blocks, threads>>>(x, w_ih, w_hh, b_ih, b_hh,
                                            fc_w, fc_b, out, S, B);
}

// round 3
// speedup vs baseline: 1.8399x; 1.3873x over previous
#include <cuda_runtime.h>

using ull = unsigned long long;

// ---------- packed f32x2 + MUFU helpers ----------
__device__ __forceinline__ ull pk2(float lo, float hi) {
    ull r; asm("mov.b64 %0, {%1, %2};" : "=l"(r) : "f"(lo), "f"(hi)); return r;
}
__device__ __forceinline__ void upk2(ull v, float& lo, float& hi) {
    asm("mov.b64 {%0, %1}, %2;" : "=f"(lo), "=f"(hi) : "l"(v));
}
__device__ __forceinline__ ull fma2(ull a, ull b, ull c) {
    ull d; asm("fma.rn.f32x2 %0, %1, %2, %3;" : "=l"(d) : "l"(a), "l"(b), "l"(c)); return d;
}
__device__ __forceinline__ ull add2(ull a, ull b) {
    ull d; asm("add.rn.f32x2 %0, %1, %2;" : "=l"(d) : "l"(a), "l"(b)); return d;
}
__device__ __forceinline__ float tanhf_hw(float x) {
    float y; asm("tanh.approx.f32 %0, %1;" : "=f"(y) : "f"(x)); return y;
}

#define HID 10

// Layout: 10 lanes per batch element (1 hidden unit per lane), 3 elems per
// 32-lane warp (lanes 30,31 duplicate work, results masked). Each lane
// computes all 4 gates for its hidden unit j with register-resident packed
// weights. Sigmoid gates use 0.5*(1+tanh(x/2)) with the 0.5 pre-scale folded
// into the packed weights, so every activation is ONE MUFU.TANH.
// One warp per block for uniform SM load (grid=1366 -> 9-10 warps/SM).
__global__ void __launch_bounds__(32, 16)
lstm_tanh_kernel(const float* __restrict__ x,
                 const float* __restrict__ w_ih,
                 const float* __restrict__ w_hh,
                 const float* __restrict__ b_ih,
                 const float* __restrict__ b_hh,
                 const float* __restrict__ fc_w,
                 const float* __restrict__ fc_b,
                 float* __restrict__ out,
                 int S, int B)
{
    const int lane = threadIdx.x & 31;
    const int wg   = blockIdx.x;

    int grp = lane / HID; if (grp > 2) grp = 2;            // lanes 30,31 -> grp 2
    int j   = lane - grp * HID; if (j >= HID) j = HID - 1; // clamp dup lanes
    const int gbase = grp * HID;

    int b = wg * 3 + grp;
    const bool live = (b < B) && (lane < 30);
    if (b >= B) b = B - 1;                                 // safe-load clamp

    // ---- per-lane packed weights (0.5 pre-scale folded into i,f,o rows) ----
    // whhA[k] = (0.5*w_hh[i-row][k], 0.5*w_hh[f-row][k])
    // whhB[k] = (    w_hh[g-row][k], 0.5*w_hh[o-row][k])
    ull whhA[HID], whhB[HID];
#pragma unroll
    for (int k = 0; k < HID; ++k) {
        whhA[k] = pk2(0.5f * w_hh[j * HID + k],
                      0.5f * w_hh[(HID + j) * HID + k]);
        whhB[k] = pk2(       w_hh[(2 * HID + j) * HID + k],
                      0.5f * w_hh[(3 * HID + j) * HID + k]);
    }
    const ull wx2A = pk2(0.5f * w_ih[j], 0.5f * w_ih[HID + j]);
    const ull wx2B = pk2(       w_ih[2 * HID + j], 0.5f * w_ih[3 * HID + j]);
    const ull b2A  = pk2(0.5f * (b_ih[j] + b_hh[j]),
                         0.5f * (b_ih[HID + j] + b_hh[HID + j]));
    const ull b2B  = pk2(        b_ih[2 * HID + j] + b_hh[2 * HID + j],
                         0.5f * (b_ih[3 * HID + j] + b_hh[3 * HID + j]));

    float fc[HID];
#pragma unroll
    for (int k = 0; k < HID; ++k) fc[k] = fc_w[k];
    const float fb = fc_b[0];

    // ---- state ----
    ull hd[HID];
#pragma unroll
    for (int k = 0; k < HID; ++k) hd[k] = 0ull;
    float c = 0.f;

    const float* xp = x + b;          // current x pointer (pointer-bumped)
    float* op = out + b;
    float xv = __ldg(xp);             // prefetch t=0

    for (int t = 0; t < S; ++t) {
        const float xt = xv;
        xp += B;
        if (t + 1 < S) xv = __ldg(xp);      // predicated prefetch, no IMAD chain

        const ull xd = pk2(xt, xt);

        // gate dot products, even/odd-k split accumulators
        ull a0 = fma2(xd, wx2A, b2A);
        ull q0 = fma2(xd, wx2B, b2B);
        ull a1 = fma2(hd[1], whhA[1], 0ull);
        ull q1 = fma2(hd[1], whhB[1], 0ull);
#pragma unroll
        for (int k = 0; k < HID; k += 2) {
            a0 = fma2(hd[k], whhA[k], a0);
            q0 = fma2(hd[k], whhB[k], q0);
        }
#pragma unroll
        for (int k = 3; k < HID; k += 2) {
            a1 = fma2(hd[k], whhA[k], a1);
            q1 = fma2(hd[k], whhB[k], q1);
        }
        const ull accA = add2(a0, a1);   // (0.5*pre_i, 0.5*pre_f)
        const ull accB = add2(q0, q1);   // (pre_g, 0.5*pre_o)

        // activations: 1 MUFU.TANH each
        float si, sf, sg, so;
        upk2(accA, si, sf);
        upk2(accB, sg, so);
        const float ia = fmaf(0.5f, tanhf_hw(si), 0.5f);
        const float fa = fmaf(0.5f, tanhf_hw(sf), 0.5f);
        const float ga = tanhf_hw(sg);
        const float oa = fmaf(0.5f, tanhf_hw(so), 0.5f);

        const float cn = fmaf(ia, ga, fa * c);
        c = cn;
        const float hn = oa * tanhf_hw(cn);

        // re-broadcast the group's 10 h values (shfl.idx, width 32)
        float hs[HID];
#pragma unroll
        for (int m = 0; m < HID; ++m)
            hs[m] = __shfl_sync(0xffffffffu, hn, gbase + m, 32);

        // output head + repack h (duplicated) for next step's packed dots
        float yv = fb;
#pragma unroll
        for (int m = 0; m < HID; ++m) {
            yv = fmaf(hs[m], fc[m], yv);
            hd[m] = pk2(hs[m], hs[m]);
        }

        if (live && j == 0) *op = yv;
        op += B;
    }
}

extern "C" void kernel_launch(void* const* d_in, const int* in_sizes, int n_in,
                              void* d_out, int out_size)
{
    const float* x    = (const float*)d_in[0];
    const float* w_ih = (const float*)d_in[1];
    const float* w_hh = (const float*)d_in[2];
    const float* b_ih = (const float*)d_in[3];
    const float* b_hh = (const float*)d_in[4];
    const float* fc_w = (const float*)d_in[5];
    const float* fc_b = (const float*)d_in[6];
    float* out = (float*)d_out;

    const int B = 4096;
    const int S = in_sizes[0] / B;   // 2048

    // one warp per block: grid 1366 -> 9-10 warps/SM, near-uniform tail
    const int blocks = (B + 2) / 3;  // 1366

    lstm_tanh_kernel<<<blocks, 32>>>(x, w_ih, w_hh, b_ih, b_hh,
                                     fc_w, fc_b, out, S, B);
}

// round 4
// speedup vs baseline: 1.9503x; 1.0600x over previous
#include <cuda_runtime.h>

using ull = unsigned long long;

// ---------- packed f32x2 + MUFU helpers ----------
__device__ __forceinline__ ull pk2(float lo, float hi) {
    ull r; asm("mov.b64 %0, {%1, %2};" : "=l"(r) : "f"(lo), "f"(hi)); return r;
}
__device__ __forceinline__ void upk2(ull v, float& lo, float& hi) {
    asm("mov.b64 {%0, %1}, %2;" : "=f"(lo), "=f"(hi) : "l"(v));
}
__device__ __forceinline__ ull fma2(ull a, ull b, ull c) {
    ull d; asm("fma.rn.f32x2 %0, %1, %2, %3;" : "=l"(d) : "l"(a), "l"(b), "l"(c)); return d;
}
__device__ __forceinline__ ull add2(ull a, ull b) {
    ull d; asm("add.rn.f32x2 %0, %1, %2;" : "=l"(d) : "l"(a), "l"(b)); return d;
}
__device__ __forceinline__ float tanhf_hw(float x) {
    float y; asm("tanh.approx.f32 %0, %1;" : "=f"(y) : "f"(x)); return y;
}

#define HID 10
#define PF  4   // x prefetch depth (steps of DRAM-latency cover)

// Layout: 10 lanes per batch element (1 hidden unit per lane), 3 elems per
// 32-lane warp (lanes 30,31 duplicate, masked). Sigmoids via
// 0.5*(1+tanh(x/2)) with the 0.5 folded into packed weights -> 1 MUFU/gate.
// Time loop unrolled x4 with a 4-deep register prefetch pipeline on x so the
// per-step DRAM load latency (~400-600cyc) is covered by ~4 steps of compute.
__global__ void __launch_bounds__(32, 12)
lstm_tanh_pf_kernel(const float* __restrict__ x,
                    const float* __restrict__ w_ih,
                    const float* __restrict__ w_hh,
                    const float* __restrict__ b_ih,
                    const float* __restrict__ b_hh,
                    const float* __restrict__ fc_w,
                    const float* __restrict__ fc_b,
                    float* __restrict__ out,
                    int S, int B)
{
    const int lane = threadIdx.x & 31;
    const int wg   = blockIdx.x;

    int grp = lane / HID; if (grp > 2) grp = 2;            // lanes 30,31 -> grp 2
    int j   = lane - grp * HID; if (j >= HID) j = HID - 1; // clamp dup lanes
    const int gbase = grp * HID;

    int b = wg * 3 + grp;
    const bool live = (b < B) && (lane < 30);
    if (b >= B) b = B - 1;                                 // safe-load clamp

    // ---- per-lane packed weights (0.5 pre-scale folded into i,f,o rows) ----
    ull whhA[HID], whhB[HID];
#pragma unroll
    for (int k = 0; k < HID; ++k) {
        whhA[k] = pk2(0.5f * w_hh[j * HID + k],
                      0.5f * w_hh[(HID + j) * HID + k]);
        whhB[k] = pk2(       w_hh[(2 * HID + j) * HID + k],
                      0.5f * w_hh[(3 * HID + j) * HID + k]);
    }
    const ull wx2A = pk2(0.5f * w_ih[j], 0.5f * w_ih[HID + j]);
    const ull wx2B = pk2(       w_ih[2 * HID + j], 0.5f * w_ih[3 * HID + j]);
    const ull b2A  = pk2(0.5f * (b_ih[j] + b_hh[j]),
                         0.5f * (b_ih[HID + j] + b_hh[HID + j]));
    const ull b2B  = pk2(        b_ih[2 * HID + j] + b_hh[2 * HID + j],
                         0.5f * (b_ih[3 * HID + j] + b_hh[3 * HID + j]));

    float fc[HID];
#pragma unroll
    for (int k = 0; k < HID; ++k) fc[k] = fc_w[k];
    const float fb = fc_b[0];

    // ---- state ----
    ull hd[HID];
#pragma unroll
    for (int k = 0; k < HID; ++k) hd[k] = 0ull;
    float c = 0.f;

    // ---- x prefetch pipeline: 4 independent loads in flight ----
    float xbuf[PF];
#pragma unroll
    for (int i = 0; i < PF; ++i) {
        int ti = (i < S) ? i : (S - 1);
        xbuf[i] = __ldg(x + (size_t)ti * B + b);
    }

    float* op = out + b;

    for (int t = 0; t < S; t += PF) {
#pragma unroll
        for (int u = 0; u < PF; ++u) {
            const float xt = xbuf[u];
            // issue prefetch for step t+u+PF (clamped; value unused past end)
            int tn = t + u + PF; tn = (tn < S) ? tn : (S - 1);
            xbuf[u] = __ldg(x + (size_t)tn * B + b);

            const ull xd = pk2(xt, xt);

            // gate dot products, even/odd-k split accumulators
            ull a0 = fma2(xd, wx2A, b2A);
            ull q0 = fma2(xd, wx2B, b2B);
            ull a1 = fma2(hd[1], whhA[1], 0ull);
            ull q1 = fma2(hd[1], whhB[1], 0ull);
#pragma unroll
            for (int k = 0; k < HID; k += 2) {
                a0 = fma2(hd[k], whhA[k], a0);
                q0 = fma2(hd[k], whhB[k], q0);
            }
#pragma unroll
            for (int k = 3; k < HID; k += 2) {
                a1 = fma2(hd[k], whhA[k], a1);
                q1 = fma2(hd[k], whhB[k], q1);
            }
            const ull accA = add2(a0, a1);   // (0.5*pre_i, 0.5*pre_f)
            const ull accB = add2(q0, q1);   // (pre_g, 0.5*pre_o)

            // activations: 1 MUFU.TANH each
            float si, sf, sg, so;
            upk2(accA, si, sf);
            upk2(accB, sg, so);
            const float ia = fmaf(0.5f, tanhf_hw(si), 0.5f);
            const float fa = fmaf(0.5f, tanhf_hw(sf), 0.5f);
            const float ga = tanhf_hw(sg);
            const float oa = fmaf(0.5f, tanhf_hw(so), 0.5f);

            const float cn = fmaf(ia, ga, fa * c);
            c = cn;
            const float hn = oa * tanhf_hw(cn);

            // re-broadcast the group's 10 h values (shfl.idx, width 32)
            float hs[HID];
#pragma unroll
            for (int m = 0; m < HID; ++m)
                hs[m] = __shfl_sync(0xffffffffu, hn, gbase + m, 32);

            // output head + repack h (duplicated) for next step's packed dots
            float yv = fb;
#pragma unroll
            for (int m = 0; m < HID; ++m) {
                yv = fmaf(hs[m], fc[m], yv);
                hd[m] = pk2(hs[m], hs[m]);
            }

            if (live && j == 0) *op = yv;
            op += B;
        }
    }
}

extern "C" void kernel_launch(void* const* d_in, const int* in_sizes, int n_in,
                              void* d_out, int out_size)
{
    const float* x    = (const float*)d_in[0];
    const float* w_ih = (const float*)d_in[1];
    const float* w_hh = (const float*)d_in[2];
    const float* b_ih = (const float*)d_in[3];
    const float* b_hh = (const float*)d_in[4];
    const float* fc_w = (const float*)d_in[5];
    const float* fc_b = (const float*)d_in[6];
    float* out = (float*)d_out;

    const int B = 4096;
    const int S = in_sizes[0] / B;   // 2048

    const int blocks = (B + 2) / 3;  // 1366 one-warp blocks, 9-10 warps/SM

    lstm_tanh_pf_kernel<<<blocks, 32>>>(x, w_ih, w_hh, b_ih, b_hh,
                                        fc_w, fc_b, out, S, B);
}